// round 2
// baseline (speedup 1.0000x reference)
#include <cuda_runtime.h>

// Dykstra alternating projection, n=4096, up to 20 iterations.
//   Xp = X + (1/n + s/n^2) - row_i/n - col_j/n ;  X <- relu(Xp)
//   stop (freeze X) once min(Xp) >= 0  (note relu(Xp)==Xp in that case)
//
// Fused design: one kernel per iteration computes the elementwise update AND
// the row/col/total reductions needed by the NEXT iteration. Col accumulators
// are triple-buffered so iteration k can zero the buffer iteration k+1
// accumulates into, without extra kernels or grid syncs.

#define NDIM 4096
#define RPB 8                         // rows per block
#define NBLK (NDIM / RPB)             // 512 blocks
#define NTHREADS 256
#define MAXIT 20
#define F4_PER_ROW (NDIM / 4)         // 1024 float4 per row
#define F4_PER_THREAD (F4_PER_ROW / NTHREADS) // 4
#define F4_ZERO_PER_BLK (F4_PER_ROW / NBLK)   // 2

__device__ float  g_row[NDIM];              // row sums (exclusive per block -> plain stores)
__device__ float4 g_col[3][F4_PER_ROW];     // col sums, triple-buffered
__device__ float  g_total[MAXIT + 1];       // per-iteration totals (atomic accum, pre-zeroed)
__device__ int    g_neg[MAXIT];             // any-negative flag per iteration

__global__ void init_kernel() {
    int t = threadIdx.x;
    for (int i = t; i < F4_PER_ROW; i += NTHREADS) {
        g_col[0][i] = make_float4(0.f, 0.f, 0.f, 0.f);
        g_col[1][i] = make_float4(0.f, 0.f, 0.f, 0.f);
    }
    if (t <= MAXIT) g_total[t] = 0.f;
    if (t < MAXIT)  g_neg[t] = 0;
}

__device__ __forceinline__ float blockReduceSum(float v) {
    __shared__ float s[NTHREADS / 32];
    #pragma unroll
    for (int o = 16; o > 0; o >>= 1) v += __shfl_down_sync(0xffffffffu, v, o);
    if ((threadIdx.x & 31) == 0) s[threadIdx.x >> 5] = v;
    __syncthreads();
    float r = 0.f;
    if (threadIdx.x < NTHREADS / 32) r = s[threadIdx.x];
    if (threadIdx.x < 32) {
        #pragma unroll
        for (int o = NTHREADS / 64; o > 0; o >>= 1)
            r += __shfl_down_sync(0xffffffffu, r, o);
    }
    __syncthreads();
    return r;  // valid on thread 0
}

// Pre-pass: row/col/total sums of the initial X (input for iteration 0).
__global__ __launch_bounds__(NTHREADS)
void reduce0_kernel(const float* __restrict__ X) {
    int t = threadIdx.x;
    int row0 = blockIdx.x * RPB;
    float4 cacc[F4_PER_THREAD];
    #pragma unroll
    for (int g = 0; g < F4_PER_THREAD; g++) cacc[g] = make_float4(0.f, 0.f, 0.f, 0.f);
    float btotal = 0.f;
    for (int r = 0; r < RPB; r++) {
        const float4* xr = (const float4*)(X + (size_t)(row0 + r) * NDIM);
        float rp = 0.f;
        #pragma unroll
        for (int g = 0; g < F4_PER_THREAD; g++) {
            float4 v = xr[t + NTHREADS * g];
            rp += (v.x + v.y) + (v.z + v.w);
            cacc[g].x += v.x; cacc[g].y += v.y; cacc[g].z += v.z; cacc[g].w += v.w;
        }
        float rs = blockReduceSum(rp);
        if (t == 0) { g_row[row0 + r] = rs; btotal += rs; }
    }
    if (t == 0) atomicAdd(&g_total[0], btotal);
    #pragma unroll
    for (int g = 0; g < F4_PER_THREAD; g++) {
        int i = t + NTHREADS * g;
        atomicAdd(&g_col[0][i].x, cacc[g].x);
        atomicAdd(&g_col[0][i].y, cacc[g].y);
        atomicAdd(&g_col[0][i].z, cacc[g].z);
        atomicAdd(&g_col[0][i].w, cacc[g].w);
    }
}

// Iteration k: update X (in place after k=0) + reductions for iteration k+1.
__global__ __launch_bounds__(NTHREADS)
void fused_kernel(const float* __restrict__ Xin, float* __restrict__ Xout,
                  int k, const int* __restrict__ max_iters) {
    __shared__ int s_done;
    __shared__ float s_rowsub[RPB];
    int t = threadIdx.x;
    int row0 = blockIdx.x * RPB;

    if (t == 0) {
        int done = (k >= *max_iters) ? 1 : 0;
        for (int j = 0; j < k; j++)
            if (g_neg[j] == 0) { done = 1; break; }
        s_done = done;
    }
    __syncthreads();
    if (s_done) {
        if (k == 0) {  // max_iters==0: output = input (robustness; never hit for 20)
            for (int r = 0; r < RPB; r++) {
                const float4* xr = (const float4*)(Xin + (size_t)(row0 + r) * NDIM);
                float4*       yr = (float4*)(Xout + (size_t)(row0 + r) * NDIM);
                #pragma unroll
                for (int g = 0; g < F4_PER_THREAD; g++)
                    yr[t + NTHREADS * g] = xr[t + NTHREADS * g];
            }
        }
        return;
    }

    const float inv_n = 1.0f / NDIM;
    float total = g_total[k];
    float c = inv_n + total * inv_n * inv_n;

    if (t < RPB) s_rowsub[t] = g_row[row0 + t] * inv_n;
    __syncthreads();

    int rdc = k % 3, wrc = (k + 1) % 3, zc = (k + 2) % 3;

    // Hoist this thread's col values (pre-scaled) — reused across all RPB rows.
    float4 cvn[F4_PER_THREAD];
    #pragma unroll
    for (int g = 0; g < F4_PER_THREAD; g++) {
        float4 cv = g_col[rdc][t + NTHREADS * g];
        cvn[g] = make_float4(cv.x * inv_n, cv.y * inv_n, cv.z * inv_n, cv.w * inv_n);
    }

    float4 cacc[F4_PER_THREAD];
    #pragma unroll
    for (int g = 0; g < F4_PER_THREAD; g++) cacc[g] = make_float4(0.f, 0.f, 0.f, 0.f);
    bool neg = false;
    float btotal = 0.f;

    for (int r = 0; r < RPB; r++) {
        const float4* xr = (const float4*)(Xin + (size_t)(row0 + r) * NDIM);
        float4*       yr = (float4*)(Xout + (size_t)(row0 + r) * NDIM);
        float a = c - s_rowsub[r];
        float rp = 0.f;
        #pragma unroll
        for (int g = 0; g < F4_PER_THREAD; g++) {
            int i = t + NTHREADS * g;
            float4 v = xr[i];
            float4 xp;
            xp.x = v.x + a - cvn[g].x;
            xp.y = v.y + a - cvn[g].y;
            xp.z = v.z + a - cvn[g].z;
            xp.w = v.w + a - cvn[g].w;
            neg = neg || (xp.x < 0.f) || (xp.y < 0.f) || (xp.z < 0.f) || (xp.w < 0.f);
            float4 y;
            y.x = fmaxf(xp.x, 0.f); y.y = fmaxf(xp.y, 0.f);
            y.z = fmaxf(xp.z, 0.f); y.w = fmaxf(xp.w, 0.f);
            yr[i] = y;
            rp += (y.x + y.y) + (y.z + y.w);
            cacc[g].x += y.x; cacc[g].y += y.y; cacc[g].z += y.z; cacc[g].w += y.w;
        }
        float rs = blockReduceSum(rp);
        if (t == 0) { g_row[row0 + r] = rs; btotal += rs; }
    }

    if (t == 0) atomicAdd(&g_total[k + 1], btotal);
    #pragma unroll
    for (int g = 0; g < F4_PER_THREAD; g++) {
        int i = t + NTHREADS * g;
        atomicAdd(&g_col[wrc][i].x, cacc[g].x);
        atomicAdd(&g_col[wrc][i].y, cacc[g].y);
        atomicAdd(&g_col[wrc][i].z, cacc[g].z);
        atomicAdd(&g_col[wrc][i].w, cacc[g].w);
    }
    if (__syncthreads_or(neg ? 1 : 0)) {
        if (t == 0) g_neg[k] = 1;   // benign multi-writer: all write 1
    }
    // Zero the col buffer iteration k+1 accumulates into (dead: last read by k-1).
    if (t < F4_ZERO_PER_BLK)
        g_col[zc][blockIdx.x * F4_ZERO_PER_BLK + t] = make_float4(0.f, 0.f, 0.f, 0.f);
}

extern "C" void kernel_launch(void* const* d_in, const int* in_sizes, int n_in,
                              void* d_out, int out_size) {
    const float* X = (const float*)d_in[0];
    const int* max_iters = (const int*)d_in[1];
    float* out = (float*)d_out;
    (void)in_sizes; (void)n_in; (void)out_size;

    init_kernel<<<1, NTHREADS>>>();
    reduce0_kernel<<<NBLK, NTHREADS>>>(X);
    for (int k = 0; k < MAXIT; k++) {
        const float* src = (k == 0) ? X : out;
        fused_kernel<<<NBLK, NTHREADS>>>(src, out, k, max_iters);
    }
}

// round 3
// speedup vs baseline: 1.0016x; 1.0016x over previous
#include <cuda_runtime.h>

// Dykstra alternating projection, n=4096, up to 20 iterations.
//   Xp = X + (1/n + s/n^2) - row_i/n - col_j/n ;  X <- relu(Xp)
//   stop (freeze X) once min(Xp) >= 0  (note relu(Xp)==Xp in that case)
//
// Fused design: one kernel per iteration computes the elementwise update AND
// the row/col/total reductions needed by the NEXT iteration. Col accumulators
// are triple-buffered so iteration k can zero the buffer iteration k+1
// accumulates into, without extra kernels or grid syncs.

#define NDIM 4096
#define RPB 8                         // rows per block
#define NBLK (NDIM / RPB)             // 512 blocks
#define NTHREADS 256
#define MAXIT 20
#define F4_PER_ROW (NDIM / 4)         // 1024 float4 per row
#define F4_PER_THREAD (F4_PER_ROW / NTHREADS) // 4
#define F4_ZERO_PER_BLK (F4_PER_ROW / NBLK)   // 2

__device__ float  g_row[NDIM];              // row sums (exclusive per block -> plain stores)
__device__ float4 g_col[3][F4_PER_ROW];     // col sums, triple-buffered
__device__ float  g_total[MAXIT + 1];       // per-iteration totals (atomic accum, pre-zeroed)
__device__ int    g_neg[MAXIT];             // any-negative flag per iteration

__global__ void init_kernel() {
    int t = threadIdx.x;
    for (int i = t; i < F4_PER_ROW; i += NTHREADS) {
        g_col[0][i] = make_float4(0.f, 0.f, 0.f, 0.f);
        g_col[1][i] = make_float4(0.f, 0.f, 0.f, 0.f);
    }
    if (t <= MAXIT) g_total[t] = 0.f;
    if (t < MAXIT)  g_neg[t] = 0;
}

__device__ __forceinline__ float blockReduceSum(float v) {
    __shared__ float s[NTHREADS / 32];
    #pragma unroll
    for (int o = 16; o > 0; o >>= 1) v += __shfl_down_sync(0xffffffffu, v, o);
    if ((threadIdx.x & 31) == 0) s[threadIdx.x >> 5] = v;
    __syncthreads();
    float r = 0.f;
    if (threadIdx.x < NTHREADS / 32) r = s[threadIdx.x];
    if (threadIdx.x < 32) {
        #pragma unroll
        for (int o = NTHREADS / 64; o > 0; o >>= 1)
            r += __shfl_down_sync(0xffffffffu, r, o);
    }
    __syncthreads();
    return r;  // valid on thread 0
}

// Pre-pass: row/col/total sums of the initial X (input for iteration 0).
__global__ __launch_bounds__(NTHREADS)
void reduce0_kernel(const float* __restrict__ X) {
    int t = threadIdx.x;
    int row0 = blockIdx.x * RPB;
    float4 cacc[F4_PER_THREAD];
    #pragma unroll
    for (int g = 0; g < F4_PER_THREAD; g++) cacc[g] = make_float4(0.f, 0.f, 0.f, 0.f);
    float btotal = 0.f;
    for (int r = 0; r < RPB; r++) {
        const float4* xr = (const float4*)(X + (size_t)(row0 + r) * NDIM);
        float rp = 0.f;
        #pragma unroll
        for (int g = 0; g < F4_PER_THREAD; g++) {
            float4 v = xr[t + NTHREADS * g];
            rp += (v.x + v.y) + (v.z + v.w);
            cacc[g].x += v.x; cacc[g].y += v.y; cacc[g].z += v.z; cacc[g].w += v.w;
        }
        float rs = blockReduceSum(rp);
        if (t == 0) { g_row[row0 + r] = rs; btotal += rs; }
    }
    if (t == 0) atomicAdd(&g_total[0], btotal);
    #pragma unroll
    for (int g = 0; g < F4_PER_THREAD; g++) {
        int i = t + NTHREADS * g;
        atomicAdd(&g_col[0][i].x, cacc[g].x);
        atomicAdd(&g_col[0][i].y, cacc[g].y);
        atomicAdd(&g_col[0][i].z, cacc[g].z);
        atomicAdd(&g_col[0][i].w, cacc[g].w);
    }
}

// Iteration k: update X (in place after k=0) + reductions for iteration k+1.
__global__ __launch_bounds__(NTHREADS)
void fused_kernel(const float* __restrict__ Xin, float* __restrict__ Xout,
                  int k, const int* __restrict__ max_iters) {
    __shared__ int s_done;
    __shared__ float s_rowsub[RPB];
    int t = threadIdx.x;
    int row0 = blockIdx.x * RPB;

    if (t == 0) {
        int done = (k >= *max_iters) ? 1 : 0;
        for (int j = 0; j < k; j++)
            if (g_neg[j] == 0) { done = 1; break; }
        s_done = done;
    }
    __syncthreads();
    if (s_done) {
        if (k == 0) {  // max_iters==0: output = input (robustness; never hit for 20)
            for (int r = 0; r < RPB; r++) {
                const float4* xr = (const float4*)(Xin + (size_t)(row0 + r) * NDIM);
                float4*       yr = (float4*)(Xout + (size_t)(row0 + r) * NDIM);
                #pragma unroll
                for (int g = 0; g < F4_PER_THREAD; g++)
                    yr[t + NTHREADS * g] = xr[t + NTHREADS * g];
            }
        }
        return;
    }

    const float inv_n = 1.0f / NDIM;
    float total = g_total[k];
    float c = inv_n + total * inv_n * inv_n;

    if (t < RPB) s_rowsub[t] = g_row[row0 + t] * inv_n;
    __syncthreads();

    int rdc = k % 3, wrc = (k + 1) % 3, zc = (k + 2) % 3;

    // Hoist this thread's col values (pre-scaled) — reused across all RPB rows.
    float4 cvn[F4_PER_THREAD];
    #pragma unroll
    for (int g = 0; g < F4_PER_THREAD; g++) {
        float4 cv = g_col[rdc][t + NTHREADS * g];
        cvn[g] = make_float4(cv.x * inv_n, cv.y * inv_n, cv.z * inv_n, cv.w * inv_n);
    }

    float4 cacc[F4_PER_THREAD];
    #pragma unroll
    for (int g = 0; g < F4_PER_THREAD; g++) cacc[g] = make_float4(0.f, 0.f, 0.f, 0.f);
    bool neg = false;
    float btotal = 0.f;

    for (int r = 0; r < RPB; r++) {
        const float4* xr = (const float4*)(Xin + (size_t)(row0 + r) * NDIM);
        float4*       yr = (float4*)(Xout + (size_t)(row0 + r) * NDIM);
        float a = c - s_rowsub[r];
        float rp = 0.f;
        #pragma unroll
        for (int g = 0; g < F4_PER_THREAD; g++) {
            int i = t + NTHREADS * g;
            float4 v = xr[i];
            float4 xp;
            xp.x = v.x + a - cvn[g].x;
            xp.y = v.y + a - cvn[g].y;
            xp.z = v.z + a - cvn[g].z;
            xp.w = v.w + a - cvn[g].w;
            neg = neg || (xp.x < 0.f) || (xp.y < 0.f) || (xp.z < 0.f) || (xp.w < 0.f);
            float4 y;
            y.x = fmaxf(xp.x, 0.f); y.y = fmaxf(xp.y, 0.f);
            y.z = fmaxf(xp.z, 0.f); y.w = fmaxf(xp.w, 0.f);
            yr[i] = y;
            rp += (y.x + y.y) + (y.z + y.w);
            cacc[g].x += y.x; cacc[g].y += y.y; cacc[g].z += y.z; cacc[g].w += y.w;
        }
        float rs = blockReduceSum(rp);
        if (t == 0) { g_row[row0 + r] = rs; btotal += rs; }
    }

    if (t == 0) atomicAdd(&g_total[k + 1], btotal);
    #pragma unroll
    for (int g = 0; g < F4_PER_THREAD; g++) {
        int i = t + NTHREADS * g;
        atomicAdd(&g_col[wrc][i].x, cacc[g].x);
        atomicAdd(&g_col[wrc][i].y, cacc[g].y);
        atomicAdd(&g_col[wrc][i].z, cacc[g].z);
        atomicAdd(&g_col[wrc][i].w, cacc[g].w);
    }
    if (__syncthreads_or(neg ? 1 : 0)) {
        if (t == 0) g_neg[k] = 1;   // benign multi-writer: all write 1
    }
    // Zero the col buffer iteration k+1 accumulates into (dead: last read by k-1).
    if (t < F4_ZERO_PER_BLK)
        g_col[zc][blockIdx.x * F4_ZERO_PER_BLK + t] = make_float4(0.f, 0.f, 0.f, 0.f);
}

extern "C" void kernel_launch(void* const* d_in, const int* in_sizes, int n_in,
                              void* d_out, int out_size) {
    const float* X = (const float*)d_in[0];
    const int* max_iters = (const int*)d_in[1];
    float* out = (float*)d_out;
    (void)in_sizes; (void)n_in; (void)out_size;

    init_kernel<<<1, NTHREADS>>>();
    reduce0_kernel<<<NBLK, NTHREADS>>>(X);
    for (int k = 0; k < MAXIT; k++) {
        const float* src = (k == 0) ? X : out;
        fused_kernel<<<NBLK, NTHREADS>>>(src, out, k, max_iters);
    }
}